// round 15
// baseline (speedup 1.0000x reference)
#include <cuda_runtime.h>
#include <cuda_bf16.h>
#include <stdint.h>
#include <math.h>

#define N_VIEW 4096
#define DIM    1024                   // elements per row (= bytes in int8)
#define N2     8192
#define INVT   14.285714285714286f    // 1/0.07
#define QS     512.0f                 // int8 quantization scale
#define SIMSC  (INVT / (QS * QS))     // s32 acc -> logit

#define BM 128
#define BN 128
#define BK 128                        // K int8 elements per stage (128 B/row)
#define KPADB 144                     // padded row stride in bytes (16B quads land conflict-free)
#define NKITER (DIM / BK)             // 8
#define NTILE  (N2 / BM)              // 64
#define NTRI   (NTILE * (NTILE + 1) / 2)   // 2080
#define POS_OFF (N_VIEW / BM)         // 32

#define TILE_BYTES  (BM * KPADB)               // 18432
#define STAGE_BYTES (2 * TILE_BYTES)           // A + B
#define SMEM_BYTES  (2 * STAGE_BYTES)          // double buffer = 73728

// ---------------- device-global scratch ----------------
__device__ uint8_t g_z8[(size_t)N2 * DIM];   // normalized rows, s8, pre-scaled by QS
__device__ float g_rowsum[N2];
__device__ float g_pos[N2];

// ---------------- PTX helpers ----------------
__device__ __forceinline__ unsigned smem_u32(const void* p) {
    return (unsigned)__cvta_generic_to_shared(p);
}
__device__ __forceinline__ void cp_async16(unsigned s, const void* g) {
    asm volatile("cp.async.cg.shared.global [%0], [%1], 16;\n" :: "r"(s), "l"(g));
}
__device__ __forceinline__ void cp_commit() {
    asm volatile("cp.async.commit_group;\n");
}
template <int N>
__device__ __forceinline__ void cp_wait() {
    asm volatile("cp.async.wait_group %0;\n" :: "n"(N));
}
__device__ __forceinline__ void ldsm_x4(unsigned addr, unsigned& r0, unsigned& r1,
                                        unsigned& r2, unsigned& r3) {
    asm volatile("ldmatrix.sync.aligned.m8n8.x4.shared.b16 {%0,%1,%2,%3}, [%4];"
                 : "=r"(r0), "=r"(r1), "=r"(r2), "=r"(r3)
                 : "r"(addr));
}
// int8 IMMA, K=32 per instruction, exact s32 accumulation
__device__ __forceinline__ void mma_s8(int* c, const unsigned* a, const unsigned* b) {
    asm volatile(
        "mma.sync.aligned.m16n8k32.row.col.s32.s8.s8.s32 "
        "{%0,%1,%2,%3}, {%4,%5,%6,%7}, {%8,%9}, {%0,%1,%2,%3};\n"
        : "+r"(c[0]), "+r"(c[1]), "+r"(c[2]), "+r"(c[3])
        : "r"(a[0]), "r"(a[1]), "r"(a[2]), "r"(a[3]), "r"(b[0]), "r"(b[1]));
}

__device__ __forceinline__ int q8(float x) {
    int v = __float2int_rn(x);
    return v < -127 ? -127 : (v > 127 ? 127 : v);
}
__device__ __forceinline__ uint32_t pack4(float a, float b, float c, float d, float s) {
    int q0 = q8(a * s), q1 = q8(b * s), q2 = q8(c * s), q3 = q8(d * s);
    return (uint32_t)(q0 & 0xFF) | ((uint32_t)(q1 & 0xFF) << 8) |
           ((uint32_t)(q2 & 0xFF) << 16) | ((uint32_t)(q3 & 0xFF) << 24);
}

// ---------------- kernel 1: warp-per-row L2-normalize -> scaled s8 ----------------
__global__ __launch_bounds__(256) void normalize_kernel(const float* __restrict__ l1,
                                                        const float* __restrict__ l2) {
    int row = blockIdx.x * 8 + (threadIdx.x >> 5);
    int lane = threadIdx.x & 31;
    const float* src = (row < N_VIEW) ? (l1 + (size_t)row * DIM)
                                      : (l2 + (size_t)(row - N_VIEW) * DIM);
    const float4* src4 = reinterpret_cast<const float4*>(src);

    float4 v[8];
    #pragma unroll
    for (int i = 0; i < 8; i++) v[i] = src4[i * 32 + lane];

    float ss = 0.f;
    #pragma unroll
    for (int i = 0; i < 8; i++)
        ss += v[i].x * v[i].x + v[i].y * v[i].y + v[i].z * v[i].z + v[i].w * v[i].w;
    #pragma unroll
    for (int o = 16; o; o >>= 1) ss += __shfl_xor_sync(0xffffffffu, ss, o);

    float scale = rsqrtf(ss) * QS;
    uint32_t* dst = reinterpret_cast<uint32_t*>(g_z8) + (size_t)row * (DIM / 4);
    #pragma unroll
    for (int i = 0; i < 8; i++)
        dst[i * 32 + lane] = pack4(v[i].x, v[i].y, v[i].z, v[i].w, scale);

    if (lane == 0) {
        g_rowsum[row] = 0.f;
        g_pos[row] = 0.f;
    }
}

// ---------------- tile loader (global -> shared via cp.async) ----------------
__device__ __forceinline__ void load_tile(const uint8_t* Abase, const uint8_t* Bbase,
                                          uint8_t* sA, uint8_t* sB,
                                          int tid, int k0) {
    #pragma unroll
    for (int h = 0; h < 4; h++) {
        int c = tid + h * 256;          // 0..1023
        int row = c >> 3;               // 128 rows
        int kq = (c & 7) * 16;          // 8 x 16B quads per row
        cp_async16(smem_u32(sA + row * KPADB + kq), Abase + (size_t)row * DIM + k0 + kq);
        cp_async16(smem_u32(sB + row * KPADB + kq), Bbase + (size_t)row * DIM + k0 + kq);
    }
    cp_commit();
}

// ---------------- kernel 2: upper-triangle int8 sim GEMM + dual-sided reduce ----------------
__global__ __launch_bounds__(256, 2) void sim_kernel() {
    extern __shared__ __align__(16) uint8_t smem[];
    // layout: [buf0: A | B][buf1: A | B]
    uint8_t* sA[2] = { smem, smem + STAGE_BYTES };
    uint8_t* sB[2] = { smem + TILE_BYTES, smem + STAGE_BYTES + TILE_BYTES };

    // linear block id -> upper-triangle tile (it <= jt)
    int u = blockIdx.x, it = 0, rem = NTILE;
    while (u >= rem) { u -= rem; it++; rem--; }
    int jt = it + u;

    int tid = threadIdx.x;
    int lane = tid & 31, wid = tid >> 5;
    int wr = wid >> 2;   // 0..1  -> 64 rows each
    int wc = wid & 3;    // 0..3  -> 32 cols each

    const uint8_t* Abase = g_z8 + (size_t)it * BM * DIM;
    const uint8_t* Bbase = g_z8 + (size_t)jt * BN * DIM;

    int acc[4][4][4];
    #pragma unroll
    for (int i = 0; i < 4; i++)
        #pragma unroll
        for (int j = 0; j < 4; j++)
            #pragma unroll
            for (int k = 0; k < 4; k++) acc[i][j][k] = 0;

    load_tile(Abase, Bbase, sA[0], sB[0], tid, 0);

    int buf = 0;
    for (int ko = 0; ko < NKITER; ko++) {
        cp_wait<0>();            // drain the load for the current buffer
        __syncthreads();         // all warps done reading buf^1 (previous compute)
        if (ko + 1 < NKITER)
            load_tile(Abase, Bbase, sA[buf ^ 1], sB[buf ^ 1], tid, (ko + 1) * BK);

        #pragma unroll
        for (int kk = 0; kk < 4; kk++) {       // four K=32 steps cover BK=128
            int kc32 = kk * 32;                // byte offset of this k32 chunk
            unsigned a[4][4];
            #pragma unroll
            for (int mt = 0; mt < 4; mt++) {
                int row = wr * 64 + mt * 16 + (lane & 15);
                int kb = kc32 + (lane >> 4) * 16;
                ldsm_x4(smem_u32(&sA[buf][row * KPADB + kb]),
                        a[mt][0], a[mt][1], a[mt][2], a[mt][3]);
            }
            unsigned b[4][2];
            #pragma unroll
            for (int p = 0; p < 2; p++) {
                int n = wc * 32 + p * 16 + (lane & 7) + (lane >> 4) * 8;
                int kb = kc32 + ((lane >> 3) & 1) * 16;
                unsigned r0, r1, r2, r3;
                ldsm_x4(smem_u32(&sB[buf][n * KPADB + kb]), r0, r1, r2, r3);
                b[2 * p][0] = r0;     b[2 * p][1] = r1;
                b[2 * p + 1][0] = r2; b[2 * p + 1][1] = r3;
            }
            #pragma unroll
            for (int mt = 0; mt < 4; mt++)
                #pragma unroll
                for (int nt = 0; nt < 4; nt++)
                    mma_s8(acc[mt][nt], a[mt], b[nt]);
        }
        buf ^= 1;
    }

    // ---- epilogue: exp, diag mask, pos capture; two-level (SMEM -> global) reduce ----
    int g = lane >> 2, t4 = lane & 3;
    int colbase = jt * BN + wc * 32;
    bool diag = (it == jt);
    bool posT = (jt == it + POS_OFF);

    // reuse tile SMEM (dead after mainloop) as reduction scratch
    __syncthreads();
    float* rsm = reinterpret_cast<float*>(smem);        // [128] row partials
    float* csm = rsm + 128;                             // [128] col partials
    rsm[tid] = 0.f;                                     // tid 0..255 zeroes both arrays
    __syncthreads();

    float cp[4][2];   // per-thread column partials: [nt][which-of-2-cols]
    #pragma unroll
    for (int nt = 0; nt < 4; nt++) { cp[nt][0] = 0.f; cp[nt][1] = 0.f; }

    #pragma unroll
    for (int mt = 0; mt < 4; mt++) {
        int lr0 = wr * 64 + mt * 16 + g;   // local row (0..127)
        int r0 = it * BM + lr0;
        int r1 = r0 + 8;
        float p0 = 0.f, p1 = 0.f;
        #pragma unroll
        for (int nt = 0; nt < 4; nt++) {
            int c0 = colbase + nt * 8 + t4 * 2;
            #pragma unroll
            for (int h = 0; h < 2; h++) {
                int c = c0 + h;
                float s0 = (float)acc[mt][nt][h] * SIMSC;
                float s1 = (float)acc[mt][nt][2 + h] * SIMSC;
                if (posT) {
                    if (c == r0 + N_VIEW) { g_pos[r0] = s0; g_pos[c] = s0; }
                    if (c == r1 + N_VIEW) { g_pos[r1] = s1; g_pos[c] = s1; }
                }
                float e0 = __expf(s0 - INVT);
                float e1 = __expf(s1 - INVT);
                if (diag) {
                    if (c == r0) e0 = 0.f;
                    if (c == r1) e1 = 0.f;
                }
                p0 += e0; p1 += e1;
                cp[nt][h] += e0 + e1;
            }
        }
        p0 += __shfl_xor_sync(0xffffffffu, p0, 1);
        p0 += __shfl_xor_sync(0xffffffffu, p0, 2);
        p1 += __shfl_xor_sync(0xffffffffu, p1, 1);
        p1 += __shfl_xor_sync(0xffffffffu, p1, 2);
        if (t4 == 0) {
            atomicAdd(&rsm[lr0], p0);
            atomicAdd(&rsm[lr0 + 8], p1);
        }
    }

    if (!diag) {
        // reduce column partials across the 8 row-groups of the warp
        #pragma unroll
        for (int off = 4; off <= 16; off <<= 1)
            #pragma unroll
            for (int nt = 0; nt < 4; nt++)
                #pragma unroll
                for (int h = 0; h < 2; h++)
                    cp[nt][h] += __shfl_xor_sync(0xffffffffu, cp[nt][h], off);
        if (g == 0) {   // lanes 0..3 hold totals for their t4's columns
            #pragma unroll
            for (int nt = 0; nt < 4; nt++) {
                int lc0 = wc * 32 + nt * 8 + t4 * 2;
                atomicAdd(&csm[lc0],     cp[nt][0]);
                atomicAdd(&csm[lc0 + 1], cp[nt][1]);
            }
        }
    }
    __syncthreads();

    // one global atomic per row (tid<128) and per col (tid>=128, off-diag only)
    if (tid < 128) {
        atomicAdd(&g_rowsum[it * BM + tid], rsm[tid]);
    } else if (!diag) {
        atomicAdd(&g_rowsum[jt * BN + (tid - 128)], csm[tid - 128]);
    }
}

// ---------------- kernel 3: finalize loss ----------------
__global__ void finalize_kernel(float* __restrict__ out) {
    int t = threadIdx.x;  // 1024
    float s = 0.f;
    #pragma unroll
    for (int i = 0; i < N2 / 1024; i++) {
        int r = t + i * 1024;
        s += INVT + __logf(g_rowsum[r]) - g_pos[r];
    }
    #pragma unroll
    for (int o = 16; o; o >>= 1) s += __shfl_xor_sync(0xffffffffu, s, o);
    __shared__ float wsum[32];
    if ((t & 31) == 0) wsum[t >> 5] = s;
    __syncthreads();
    if (t < 32) {
        float tot = wsum[t];
        #pragma unroll
        for (int o = 16; o; o >>= 1) tot += __shfl_xor_sync(0xffffffffu, tot, o);
        if (t == 0) out[0] = tot / (float)N2;
    }
}

// ---------------- launch ----------------
extern "C" void kernel_launch(void* const* d_in, const int* in_sizes, int n_in,
                              void* d_out, int out_size) {
    const float* l1 = (const float*)d_in[0];
    const float* l2 = (const float*)d_in[1];

    cudaFuncSetAttribute(sim_kernel, cudaFuncAttributeMaxDynamicSharedMemorySize, SMEM_BYTES);

    normalize_kernel<<<N2 / 8, 256>>>(l1, l2);
    sim_kernel<<<NTRI, 256, SMEM_BYTES>>>();
    finalize_kernel<<<1, 1024>>>((float*)d_out);
}

// round 16
// speedup vs baseline: 1.0504x; 1.0504x over previous
#include <cuda_runtime.h>
#include <cuda_bf16.h>
#include <stdint.h>
#include <math.h>

#define N_VIEW 4096
#define DIM    1024                   // elements per row (= bytes in int8)
#define N2     8192
#define INVT   14.285714285714286f    // 1/0.07
#define QS     512.0f                 // int8 quantization scale
#define SIMSC  (INVT / (QS * QS))     // s32 acc -> logit

#define BM 128
#define BN 128
#define BK 128                        // K int8 elements per stage (128 B/row)
#define KPADB 144                     // padded row stride in bytes (16B quads land conflict-free)
#define NKITER (DIM / BK)             // 8
#define NTILE  (N2 / BM)              // 64
#define NTRI   (NTILE * (NTILE + 1) / 2)   // 2080
#define POS_OFF (N_VIEW / BM)         // 32

#define TILE_BYTES  (BM * KPADB)               // 18432
#define STAGE_BYTES (2 * TILE_BYTES)           // A + B
#define SMEM_BYTES  (2 * STAGE_BYTES)          // double buffer = 73728

// ---------------- device-global scratch ----------------
__device__ uint8_t g_z8[(size_t)N2 * DIM];   // normalized rows, s8, pre-scaled by QS
__device__ float g_rowsum[N2];
__device__ float g_pos[N2];

// ---------------- PTX helpers ----------------
__device__ __forceinline__ unsigned smem_u32(const void* p) {
    return (unsigned)__cvta_generic_to_shared(p);
}
__device__ __forceinline__ void cp_async16(unsigned s, const void* g) {
    asm volatile("cp.async.cg.shared.global [%0], [%1], 16;\n" :: "r"(s), "l"(g));
}
__device__ __forceinline__ void cp_commit() {
    asm volatile("cp.async.commit_group;\n");
}
template <int N>
__device__ __forceinline__ void cp_wait() {
    asm volatile("cp.async.wait_group %0;\n" :: "n"(N));
}
__device__ __forceinline__ void ldsm_x4(unsigned addr, unsigned& r0, unsigned& r1,
                                        unsigned& r2, unsigned& r3) {
    asm volatile("ldmatrix.sync.aligned.m8n8.x4.shared.b16 {%0,%1,%2,%3}, [%4];"
                 : "=r"(r0), "=r"(r1), "=r"(r2), "=r"(r3)
                 : "r"(addr));
}
// int8 IMMA, K=32 per instruction, exact s32 accumulation
__device__ __forceinline__ void mma_s8(int* c, const unsigned* a, const unsigned* b) {
    asm volatile(
        "mma.sync.aligned.m16n8k32.row.col.s32.s8.s8.s32 "
        "{%0,%1,%2,%3}, {%4,%5,%6,%7}, {%8,%9}, {%0,%1,%2,%3};\n"
        : "+r"(c[0]), "+r"(c[1]), "+r"(c[2]), "+r"(c[3])
        : "r"(a[0]), "r"(a[1]), "r"(a[2]), "r"(a[3]), "r"(b[0]), "r"(b[1]));
}

__device__ __forceinline__ int q8(float x) {
    int v = __float2int_rn(x);
    return v < -127 ? -127 : (v > 127 ? 127 : v);
}
__device__ __forceinline__ uint32_t pack4(float a, float b, float c, float d, float s) {
    int q0 = q8(a * s), q1 = q8(b * s), q2 = q8(c * s), q3 = q8(d * s);
    return (uint32_t)(q0 & 0xFF) | ((uint32_t)(q1 & 0xFF) << 8) |
           ((uint32_t)(q2 & 0xFF) << 16) | ((uint32_t)(q3 & 0xFF) << 24);
}

// ---------------- kernel 1: warp-per-row L2-normalize -> scaled s8 ----------------
__global__ __launch_bounds__(256) void normalize_kernel(const float* __restrict__ l1,
                                                        const float* __restrict__ l2) {
    int row = blockIdx.x * 8 + (threadIdx.x >> 5);
    int lane = threadIdx.x & 31;
    const float* src = (row < N_VIEW) ? (l1 + (size_t)row * DIM)
                                      : (l2 + (size_t)(row - N_VIEW) * DIM);
    const float4* src4 = reinterpret_cast<const float4*>(src);

    float4 v[8];
    #pragma unroll
    for (int i = 0; i < 8; i++) v[i] = src4[i * 32 + lane];

    float ss = 0.f;
    #pragma unroll
    for (int i = 0; i < 8; i++)
        ss += v[i].x * v[i].x + v[i].y * v[i].y + v[i].z * v[i].z + v[i].w * v[i].w;
    #pragma unroll
    for (int o = 16; o; o >>= 1) ss += __shfl_xor_sync(0xffffffffu, ss, o);

    float scale = rsqrtf(ss) * QS;
    uint32_t* dst = reinterpret_cast<uint32_t*>(g_z8) + (size_t)row * (DIM / 4);
    #pragma unroll
    for (int i = 0; i < 8; i++)
        dst[i * 32 + lane] = pack4(v[i].x, v[i].y, v[i].z, v[i].w, scale);

    if (lane == 0) {
        g_rowsum[row] = 0.f;
        g_pos[row] = 0.f;
    }
}

// ---------------- tile loader (global -> shared via cp.async) ----------------
// Stage: A = 128 rows x 128 B and B = 128 rows x 128 B, row stride KPADB.
__device__ __forceinline__ void load_tile(const uint8_t* Abase, const uint8_t* Bbase,
                                          uint8_t* sA, uint8_t* sB,
                                          int tid, int k0) {
    #pragma unroll
    for (int h = 0; h < 4; h++) {
        int c = tid + h * 256;          // 0..1023
        int row = c >> 3;               // 128 rows
        int kq = (c & 7) * 16;          // 8 x 16B quads per row
        cp_async16(smem_u32(sA + row * KPADB + kq), Abase + (size_t)row * DIM + k0 + kq);
        cp_async16(smem_u32(sB + row * KPADB + kq), Bbase + (size_t)row * DIM + k0 + kq);
    }
    cp_commit();
}

// ---------------- kernel 2: upper-triangle int8 sim GEMM + dual-sided reduce ----------------
__global__ __launch_bounds__(256, 2) void sim_kernel() {
    extern __shared__ __align__(16) uint8_t smem[];
    // layout: [buf0: A | B][buf1: A | B]
    uint8_t* sA[2] = { smem, smem + STAGE_BYTES };
    uint8_t* sB[2] = { smem + TILE_BYTES, smem + STAGE_BYTES + TILE_BYTES };

    // linear block id -> upper-triangle tile (it <= jt)
    int u = blockIdx.x, it = 0, rem = NTILE;
    while (u >= rem) { u -= rem; it++; rem--; }
    int jt = it + u;

    int tid = threadIdx.x;
    int lane = tid & 31, wid = tid >> 5;
    int wr = wid >> 2;   // 0..1  -> 64 rows each
    int wc = wid & 3;    // 0..3  -> 32 cols each

    const uint8_t* Abase = g_z8 + (size_t)it * BM * DIM;
    const uint8_t* Bbase = g_z8 + (size_t)jt * BN * DIM;

    int acc[4][4][4];
    #pragma unroll
    for (int i = 0; i < 4; i++)
        #pragma unroll
        for (int j = 0; j < 4; j++)
            #pragma unroll
            for (int k = 0; k < 4; k++) acc[i][j][k] = 0;

    load_tile(Abase, Bbase, sA[0], sB[0], tid, 0);

    int buf = 0;
    for (int ko = 0; ko < NKITER; ko++) {
        cp_wait<0>();            // drain the load for the current buffer
        __syncthreads();         // all warps done reading buf^1 (previous compute)
        if (ko + 1 < NKITER)
            load_tile(Abase, Bbase, sA[buf ^ 1], sB[buf ^ 1], tid, (ko + 1) * BK);

        #pragma unroll
        for (int kk = 0; kk < 4; kk++) {       // four K=32 steps cover BK=128
            int kc32 = kk * 32;                // byte offset of this k32 chunk
            unsigned a[4][4];
            #pragma unroll
            for (int mt = 0; mt < 4; mt++) {
                int row = wr * 64 + mt * 16 + (lane & 15);
                int kb = kc32 + (lane >> 4) * 16;
                ldsm_x4(smem_u32(&sA[buf][row * KPADB + kb]),
                        a[mt][0], a[mt][1], a[mt][2], a[mt][3]);
            }
            unsigned b[4][2];
            #pragma unroll
            for (int p = 0; p < 2; p++) {
                int n = wc * 32 + p * 16 + (lane & 7) + (lane >> 4) * 8;
                int kb = kc32 + ((lane >> 3) & 1) * 16;
                unsigned r0, r1, r2, r3;
                ldsm_x4(smem_u32(&sB[buf][n * KPADB + kb]), r0, r1, r2, r3);
                b[2 * p][0] = r0;     b[2 * p][1] = r1;
                b[2 * p + 1][0] = r2; b[2 * p + 1][1] = r3;
            }
            #pragma unroll
            for (int mt = 0; mt < 4; mt++)
                #pragma unroll
                for (int nt = 0; nt < 4; nt++)
                    mma_s8(acc[mt][nt], a[mt], b[nt]);
        }
        buf ^= 1;
    }

    // ---- epilogue: exp, diag mask, pos capture, row + column (mirror) sums ----
    int g = lane >> 2, t4 = lane & 3;
    int rowbase = it * BM + wr * 64;
    int colbase = jt * BN + wc * 32;
    bool diag = (it == jt);
    bool posT = (jt == it + POS_OFF);

    float cp[4][2];   // per-thread column partials: [nt][which-of-2-cols]
    #pragma unroll
    for (int nt = 0; nt < 4; nt++) { cp[nt][0] = 0.f; cp[nt][1] = 0.f; }

    #pragma unroll
    for (int mt = 0; mt < 4; mt++) {
        int r0 = rowbase + mt * 16 + g;
        int r1 = r0 + 8;
        float p0 = 0.f, p1 = 0.f;
        #pragma unroll
        for (int nt = 0; nt < 4; nt++) {
            int c0 = colbase + nt * 8 + t4 * 2;
            #pragma unroll
            for (int h = 0; h < 2; h++) {
                int c = c0 + h;
                float s0 = (float)acc[mt][nt][h] * SIMSC;
                float s1 = (float)acc[mt][nt][2 + h] * SIMSC;
                if (posT) {
                    if (c == r0 + N_VIEW) { g_pos[r0] = s0; g_pos[c] = s0; }
                    if (c == r1 + N_VIEW) { g_pos[r1] = s1; g_pos[c] = s1; }
                }
                float e0 = __expf(s0 - INVT);
                float e1 = __expf(s1 - INVT);
                if (diag) {
                    if (c == r0) e0 = 0.f;
                    if (c == r1) e1 = 0.f;
                }
                p0 += e0; p1 += e1;
                cp[nt][h] += e0 + e1;
            }
        }
        p0 += __shfl_xor_sync(0xffffffffu, p0, 1);
        p0 += __shfl_xor_sync(0xffffffffu, p0, 2);
        p1 += __shfl_xor_sync(0xffffffffu, p1, 1);
        p1 += __shfl_xor_sync(0xffffffffu, p1, 2);
        if (t4 == 0) {
            atomicAdd(&g_rowsum[r0], p0);
            atomicAdd(&g_rowsum[r1], p1);
        }
    }

    if (!diag) {
        // reduce column partials across the 8 row-groups of the warp
        #pragma unroll
        for (int off = 4; off <= 16; off <<= 1)
            #pragma unroll
            for (int nt = 0; nt < 4; nt++)
                #pragma unroll
                for (int h = 0; h < 2; h++)
                    cp[nt][h] += __shfl_xor_sync(0xffffffffu, cp[nt][h], off);
        if (g == 0) {   // lanes 0..3 hold totals for their t4's columns
            #pragma unroll
            for (int nt = 0; nt < 4; nt++) {
                int c0 = colbase + nt * 8 + t4 * 2;
                atomicAdd(&g_rowsum[c0],     cp[nt][0]);
                atomicAdd(&g_rowsum[c0 + 1], cp[nt][1]);
            }
        }
    }
}

// ---------------- kernel 3: finalize loss ----------------
__global__ void finalize_kernel(float* __restrict__ out) {
    int t = threadIdx.x;  // 1024
    float s = 0.f;
    #pragma unroll
    for (int i = 0; i < N2 / 1024; i++) {
        int r = t + i * 1024;
        s += INVT + __logf(g_rowsum[r]) - g_pos[r];
    }
    #pragma unroll
    for (int o = 16; o; o >>= 1) s += __shfl_xor_sync(0xffffffffu, s, o);
    __shared__ float wsum[32];
    if ((t & 31) == 0) wsum[t >> 5] = s;
    __syncthreads();
    if (t < 32) {
        float tot = wsum[t];
        #pragma unroll
        for (int o = 16; o; o >>= 1) tot += __shfl_xor_sync(0xffffffffu, tot, o);
        if (t == 0) out[0] = tot / (float)N2;
    }
}

// ---------------- launch ----------------
extern "C" void kernel_launch(void* const* d_in, const int* in_sizes, int n_in,
                              void* d_out, int out_size) {
    const float* l1 = (const float*)d_in[0];
    const float* l2 = (const float*)d_in[1];

    cudaFuncSetAttribute(sim_kernel, cudaFuncAttributeMaxDynamicSharedMemorySize, SMEM_BYTES);

    normalize_kernel<<<N2 / 8, 256>>>(l1, l2);
    sim_kernel<<<NTRI, 256, SMEM_BYTES>>>();
    finalize_kernel<<<1, 1024>>>((float*)d_out);
}